// round 1
// baseline (speedup 1.0000x reference)
#include <cuda_runtime.h>
#include <cuda_bf16.h>

#define NUM_USERS 100000
#define NUM_ITEMS 200000
#define NN        (NUM_USERS + NUM_ITEMS)   // 300000
#define D         64
#define NNZ       5000000
#define BATCH     16384

// Scratch: layer-1/2/3 embeddings (each 300000 x 64 f32 = 76.8 MB)
__device__ float g_A[(size_t)NN * D];
__device__ float g_B[(size_t)NN * D];
__device__ float g_C[(size_t)NN * D];

// Zero all three scratch buffers (one float4 per buffer per thread).
__global__ void zero3_kernel() {
    long long i = (long long)blockIdx.x * blockDim.x + threadIdx.x;
    const long long n4 = (long long)NN * D / 4;
    if (i < n4) {
        float4 z = make_float4(0.f, 0.f, 0.f, 0.f);
        reinterpret_cast<float4*>(g_A)[i] = z;
        reinterpret_cast<float4*>(g_B)[i] = z;
        reinterpret_cast<float4*>(g_C)[i] = z;
    }
}

// One SpMM layer: dst[row] += val * src[col]  (COO scatter-add).
// Thread handles (edge e, quad q): 16 threads per edge, float4 per thread.
// stage 0: src = (user_emb, item_emb) split; stage 1: src = g_A; stage 2: src = g_B.
__global__ void spmm_kernel(const int*   __restrict__ erow,
                            const int*   __restrict__ ecol,
                            const float* __restrict__ evals,
                            const float* __restrict__ uemb,
                            const float* __restrict__ iemb,
                            int stage) {
    long long idx = (long long)blockIdx.x * blockDim.x + threadIdx.x;
    if (idx >= (long long)NNZ * 16) return;
    int e = (int)(idx >> 4);
    int q = (int)(idx & 15);

    int   col = __ldg(ecol + e);
    int   row = __ldg(erow + e);
    float v   = __ldg(evals + e);

    const float* src_u;
    const float* src_i;   // pointer such that item row = src_i + (col - NUM_USERS)*D
    float*       dst;
    if (stage == 0)      { src_u = uemb;  src_i = iemb;                        dst = g_A; }
    else if (stage == 1) { src_u = g_A;   src_i = g_A + (size_t)NUM_USERS * D; dst = g_B; }
    else                 { src_u = g_B;   src_i = g_B + (size_t)NUM_USERS * D; dst = g_C; }

    const float* srow = (col < NUM_USERS)
                      ? (src_u + (size_t)col * D)
                      : (src_i + (size_t)(col - NUM_USERS) * D);

    float4 x = *reinterpret_cast<const float4*>(srow + q * 4);
    float4 m = make_float4(v * x.x, v * x.y, v * x.z, v * x.w);

    float* daddr = dst + (size_t)row * D + q * 4;
    asm volatile("red.global.add.v4.f32 [%0], {%1, %2, %3, %4};"
                 :: "l"(daddr), "f"(m.x), "f"(m.y), "f"(m.z), "f"(m.w)
                 : "memory");
}

// gamma[b] = dot( (e0_u + A_u + B_u + C_u)/4 , (e0_i + A_i + B_i + C_i)/4 )
// One warp per pair; each lane covers d = lane and d = lane + 32.
__global__ void final_kernel(const int*   __restrict__ users,
                             const int*   __restrict__ items,
                             const float* __restrict__ uemb,
                             const float* __restrict__ iemb,
                             float*       __restrict__ out) {
    int warp = (blockIdx.x * blockDim.x + threadIdx.x) >> 5;
    int lane = threadIdx.x & 31;
    if (warp >= BATCH) return;

    int u  = __ldg(users + warp);
    int it = __ldg(items + warp);

    size_t urow = (size_t)u * D;                    // global index u (user block)
    size_t irow = (size_t)(NUM_USERS + it) * D;     // global index of item
    size_t u0   = (size_t)u * D;                    // into user_emb
    size_t i0   = (size_t)it * D;                   // into item_emb

    float dot = 0.f;
#pragma unroll
    for (int k = 0; k < 2; k++) {
        int d = lane + k * 32;
        float uv = __ldg(uemb + u0 + d) + g_A[urow + d] + g_B[urow + d] + g_C[urow + d];
        float iv = __ldg(iemb + i0 + d) + g_A[irow + d] + g_B[irow + d] + g_C[irow + d];
        dot += uv * iv;
    }
    // (uv/4)*(iv/4) summed  ->  dot/16
#pragma unroll
    for (int off = 16; off > 0; off >>= 1)
        dot += __shfl_xor_sync(0xFFFFFFFFu, dot, off);

    if (lane == 0) out[warp] = dot * 0.0625f;
}

extern "C" void kernel_launch(void* const* d_in, const int* in_sizes, int n_in,
                              void* d_out, int out_size) {
    const int*   users = (const int*)  d_in[0];
    const int*   items = (const int*)  d_in[1];
    const int*   erow  = (const int*)  d_in[2];
    const int*   ecol  = (const int*)  d_in[3];
    const float* evals = (const float*)d_in[4];
    const float* uemb  = (const float*)d_in[5];
    const float* iemb  = (const float*)d_in[6];
    // d_in[7] = n_layers (fixed = 3)
    float* out = (float*)d_out;

    // Zero scratch
    {
        long long n4 = (long long)NN * D / 4;   // 4.8M
        int threads = 256;
        int blocks  = (int)((n4 + threads - 1) / threads);
        zero3_kernel<<<blocks, threads>>>();
    }

    // 3 SpMM layers
    {
        long long total = (long long)NNZ * 16;  // 80M threads
        int threads = 256;
        int blocks  = (int)((total + threads - 1) / threads);
        spmm_kernel<<<blocks, threads>>>(erow, ecol, evals, uemb, iemb, 0);
        spmm_kernel<<<blocks, threads>>>(erow, ecol, evals, uemb, iemb, 1);
        spmm_kernel<<<blocks, threads>>>(erow, ecol, evals, uemb, iemb, 2);
    }

    // Final gather + dot
    {
        int threads = 256;                       // 8 warps/block
        int blocks  = (BATCH + 7) / 8;
        final_kernel<<<blocks, threads>>>(users, items, uemb, iemb, out);
    }
}

// round 4
// speedup vs baseline: 1.9314x; 1.9314x over previous
#include <cuda_runtime.h>
#include <cuda_bf16.h>

#define NUM_USERS 100000
#define NUM_ITEMS 200000
#define NN        (NUM_USERS + NUM_ITEMS)   // 300000
#define D         64
#define NNZ       5000000
#define BATCH     16384
#define WIDTH     64                         // ELL width
#define MAX_SPILL 4096

// Layer outputs (each 300000 x 64 f32 = 76.8 MB)
__device__ float g_A[(size_t)NN * D];
__device__ float g_B[(size_t)NN * D];
__device__ float g_C[(size_t)NN * D];

// ELL storage: packed (col, val_bits) per slot. 300000*64*8B = 153.6 MB
__device__ int2 g_ell[(size_t)NN * WIDTH];
__device__ int  g_len[NN];

// Spill safety net (degree > WIDTH; expected empty for this dataset)
__device__ int   g_spill_count;
__device__ int   g_srow[MAX_SPILL];
__device__ int   g_scol[MAX_SPILL];
__device__ float g_sval[MAX_SPILL];

// ---------------------------------------------------------------------------
__global__ void ell_zero_kernel() {
    int i = blockIdx.x * blockDim.x + threadIdx.x;
    if (i < NN) g_len[i] = 0;
    if (i == 0) g_spill_count = 0;
}

__global__ void ell_fill_kernel(const int*   __restrict__ erow,
                                const int*   __restrict__ ecol,
                                const float* __restrict__ evals) {
    int i = blockIdx.x * blockDim.x + threadIdx.x;
    if (i >= NNZ) return;
    int   row = erow[i];
    int   col = ecol[i];
    float val = evals[i];
    int pos = atomicAdd(&g_len[row], 1);
    if (pos < WIDTH) {
        g_ell[(size_t)row * WIDTH + pos] = make_int2(col, __float_as_int(val));
    } else {
        int s = atomicAdd(&g_spill_count, 1);
        if (s < MAX_SPILL) {
            g_srow[s] = row;
            g_scol[s] = col;
            g_sval[s] = val;
        }
    }
}

// ---------------------------------------------------------------------------
// Select src (split user/item pointers) and dst from the stage, DEVICE-side.
// stage 0: src = (uemb, iemb), dst = g_A
// stage 1: src = g_A,          dst = g_B
// stage 2: src = g_B,          dst = g_C
__device__ __forceinline__ void stage_ptrs(int stage,
                                           const float* uemb, const float* iemb,
                                           const float*& su, const float*& si,
                                           float*& dst) {
    if (stage == 0)      { su = uemb; si = iemb;                        dst = g_A; }
    else if (stage == 1) { su = g_A;  si = g_A + (size_t)NUM_USERS * D; dst = g_B; }
    else                 { su = g_B;  si = g_B + (size_t)NUM_USERS * D; dst = g_C; }
}

// ELL SpMM: one warp per destination row; lane owns dims {2*lane, 2*lane+1}.
// dst[row] = sum over ELL entries of val * src[col]. No atomics.
__global__ void spmm_ell_kernel(const float* __restrict__ uemb,
                                const float* __restrict__ iemb,
                                int stage) {
    int warp = (blockIdx.x * blockDim.x + threadIdx.x) >> 5;
    int lane = threadIdx.x & 31;
    if (warp >= NN) return;

    const float* su; const float* si; float* dst;
    stage_ptrs(stage, uemb, iemb, su, si, dst);

    int len = min(g_len[warp], WIDTH);
    const int2* erow = g_ell + (size_t)warp * WIDTH;

    float2 acc = make_float2(0.f, 0.f);
    for (int base = 0; base < len; base += 32) {
        int n = min(32, len - base);
        int2 ev = make_int2(0, 0);
        if (base + lane < len)
            ev = erow[base + lane];
        for (int j = 0; j < n; j++) {
            int   cj = __shfl_sync(0xFFFFFFFFu, ev.x, j);
            float vj = __int_as_float(__shfl_sync(0xFFFFFFFFu, ev.y, j));
            const float* srow = (cj < NUM_USERS)
                              ? (su + (size_t)cj * D)
                              : (si + (size_t)(cj - NUM_USERS) * D);
            float2 x = *reinterpret_cast<const float2*>(srow + 2 * lane);
            acc.x += vj * x.x;
            acc.y += vj * x.y;
        }
    }
    *reinterpret_cast<float2*>(dst + (size_t)warp * D + 2 * lane) = acc;
}

// Spill mop-up: adds dropped edges into dst with vector atomics.
// 16 threads per spill edge. No-op when g_spill_count == 0.
__global__ void spill_kernel(const float* __restrict__ uemb,
                             const float* __restrict__ iemb,
                             int stage) {
    int cnt = min(g_spill_count, MAX_SPILL);
    int idx = blockIdx.x * blockDim.x + threadIdx.x;
    int e = idx >> 4;
    int q = idx & 15;
    if (e >= cnt) return;

    const float* su; const float* si; float* dst;
    stage_ptrs(stage, uemb, iemb, su, si, dst);

    int   row = g_srow[e];
    int   col = g_scol[e];
    float v   = g_sval[e];
    const float* srow = (col < NUM_USERS)
                      ? (su + (size_t)col * D)
                      : (si + (size_t)(col - NUM_USERS) * D);
    float4 x = *reinterpret_cast<const float4*>(srow + q * 4);
    float* daddr = dst + (size_t)row * D + q * 4;
    asm volatile("red.global.add.v4.f32 [%0], {%1, %2, %3, %4};"
                 :: "l"(daddr), "f"(v * x.x), "f"(v * x.y), "f"(v * x.z), "f"(v * x.w)
                 : "memory");
}

// ---------------------------------------------------------------------------
// gamma[b] = dot( (e0_u+A_u+B_u+C_u)/4 , (e0_i+A_i+B_i+C_i)/4 )
__global__ void final_kernel(const int*   __restrict__ users,
                             const int*   __restrict__ items,
                             const float* __restrict__ uemb,
                             const float* __restrict__ iemb,
                             float*       __restrict__ out) {
    int warp = (blockIdx.x * blockDim.x + threadIdx.x) >> 5;
    int lane = threadIdx.x & 31;
    if (warp >= BATCH) return;

    int u  = __ldg(users + warp);
    int it = __ldg(items + warp);

    size_t urow = (size_t)u * D;
    size_t irow = (size_t)(NUM_USERS + it) * D;
    size_t u0   = (size_t)u * D;
    size_t i0   = (size_t)it * D;

    float dot = 0.f;
#pragma unroll
    for (int k = 0; k < 2; k++) {
        int d = lane + k * 32;
        float uv = __ldg(uemb + u0 + d) + g_A[urow + d] + g_B[urow + d] + g_C[urow + d];
        float iv = __ldg(iemb + i0 + d) + g_A[irow + d] + g_B[irow + d] + g_C[irow + d];
        dot += uv * iv;
    }
#pragma unroll
    for (int off = 16; off > 0; off >>= 1)
        dot += __shfl_xor_sync(0xFFFFFFFFu, dot, off);

    if (lane == 0) out[warp] = dot * 0.0625f;   // (1/4)*(1/4)
}

// ---------------------------------------------------------------------------
extern "C" void kernel_launch(void* const* d_in, const int* in_sizes, int n_in,
                              void* d_out, int out_size) {
    const int*   users = (const int*)  d_in[0];
    const int*   items = (const int*)  d_in[1];
    const int*   erow  = (const int*)  d_in[2];
    const int*   ecol  = (const int*)  d_in[3];
    const float* evals = (const float*)d_in[4];
    const float* uemb  = (const float*)d_in[5];
    const float* iemb  = (const float*)d_in[6];
    float* out = (float*)d_out;

    // --- build ELL (device-symbol access only inside kernels) ---
    ell_zero_kernel<<<(NN + 255) / 256, 256>>>();
    ell_fill_kernel<<<(NNZ + 255) / 256, 256>>>(erow, ecol, evals);

    // --- 3 SpMM layers ---
    int threads = 256;                         // 8 warps/block
    int blocks  = (NN + 7) / 8;                // 37500
    int sblocks = (MAX_SPILL * 16 + 255) / 256;

    spmm_ell_kernel<<<blocks, threads>>>(uemb, iemb, 0);
    spill_kernel<<<sblocks, 256>>>(uemb, iemb, 0);

    spmm_ell_kernel<<<blocks, threads>>>(uemb, iemb, 1);
    spill_kernel<<<sblocks, 256>>>(uemb, iemb, 1);

    spmm_ell_kernel<<<blocks, threads>>>(uemb, iemb, 2);
    spill_kernel<<<sblocks, 256>>>(uemb, iemb, 2);

    // --- final gather + dot ---
    final_kernel<<<(BATCH + 7) / 8, 256>>>(users, items, uemb, iemb, out);
}